// round 15
// baseline (speedup 1.0000x reference)
#include <cuda_runtime.h>
#include <cstdint>

#define T_STEPS   256
#define BATCH     32
#define N_INP     28
#define N_HID     1024
#define N_OUT     10
#define NCTA      128
#define N_RT      64         // row tiles
#define ROWS_CTA  16         // rows per CTA
#define B_CTA     16         // batches per CTA
#define TPB       512        // 16 warps, warp w owns 64 j
#define TWO_PI_F  6.283185307179586f

typedef unsigned long long u64;

// ---------------- device globals ----------------
__device__ float g_inp[T_STEPS * N_HID * BATCH];            // [t][h][b]
// one X buffer per step: no WAR hazard ever (written once, read once per replay)
__device__ __align__(256) u64 gX64[(T_STEPS + 1)][N_HID][BATCH];  // [t][j][b] = pack(cos,sin)
__device__ unsigned g_flags[NCTA * 8];                      // final-barrier flags
__device__ unsigned g_pf[NCTA * 8];                         // publish counters [bt*64+rt]*8
__device__ float g_rout[BATCH * N_OUT * N_RT];              // readout partials

// packed f32x2 ops
#define FMA2(acc, a, b) \
    asm("fma.rn.f32x2 %0, %1, %2, %0;" : "+l"(acc) : "l"(a), "l"(b))
#define ADD2(acc, b) \
    asm("add.rn.f32x2 %0, %0, %1;" : "+l"(acc) : "l"(b))

__device__ __forceinline__ u64 pack2(float lo, float hi) {
    u64 r;
    asm("mov.b64 %0, {%1, %2};" : "=l"(r) : "f"(lo), "f"(hi));
    return r;
}
__device__ __forceinline__ float lo32(u64 v) { return __uint_as_float((unsigned)v); }
__device__ __forceinline__ float hi32(u64 v) { return __uint_as_float((unsigned)(v >> 32)); }

__device__ __forceinline__ unsigned ld_acq(const unsigned* p) {
    unsigned v;
    asm volatile("ld.global.acquire.gpu.u32 %0, [%1];" : "=r"(v) : "l"(p) : "memory");
    return v;
}
__device__ __forceinline__ void st_rel(unsigned* p, unsigned v) {
    asm volatile("st.global.release.gpu.u32 [%0], %1;" :: "l"(p), "r"(v) : "memory");
}
__device__ __forceinline__ void red_add_rel(unsigned* p, unsigned v) {
    asm volatile("red.release.gpu.global.add.u32 [%0], %1;" :: "l"(p), "r"(v) : "memory");
}

// single-flag wait, uniform across warp, HW-sleep backoff capped at 128ns
__device__ __forceinline__ void wait_flag(const unsigned* fp, unsigned need) {
    if (ld_acq(fp) >= need) return;            // steady-state fast path
    unsigned ns = 32;
    do {
        __nanosleep(ns);
        if (ns < 128) ns <<= 1;
    } while (ld_acq(fp) < need);
}

// ---------------- final grid barrier (used once, for readout) ---------------
__device__ __forceinline__ void grid_barrier(int tid, int cta, unsigned target) {
    __syncthreads();
    if (tid < 32) {
        if (tid == 0) st_rel(&g_flags[cta * 8], target);
        const unsigned* p0 = &g_flags[(tid +  0) * 8];
        const unsigned* p1 = &g_flags[(tid + 32) * 8];
        const unsigned* p2 = &g_flags[(tid + 64) * 8];
        const unsigned* p3 = &g_flags[(tid + 96) * 8];
        bool pending;
        do {
            pending = (ld_acq(p0) < target) | (ld_acq(p1) < target) |
                      (ld_acq(p2) < target) | (ld_acq(p3) < target);
            if (pending) __nanosleep(64);
        } while (__any_sync(0xFFFFFFFFu, pending));
    }
    __syncthreads();
}

// ---------------- kernel A: input projection + flag reset -------------------
__global__ void __launch_bounds__(256)
prep_kernel(const float* __restrict__ x,
            const float* __restrict__ Wi_w,
            const float* __restrict__ Wi_b,
            const float* __restrict__ omega) {
    int t   = blockIdx.y;
    int hg  = blockIdx.x;
    int tid = threadIdx.x;
    int w   = tid >> 5;
    int b   = tid & 31;

    if (t == 0 && hg == 0 && tid < NCTA) {
        g_flags[tid * 8] = 0;
        g_pf[tid * 8]    = 0;
    }

    float4 xq[7];
    const float4* xrow = (const float4*)(x + (size_t)t * BATCH * N_INP + b * N_INP);
#pragma unroll
    for (int q = 0; q < 7; q++) xq[q] = xrow[q];

    int h0 = hg * 256 + w * 32;
    for (int hh = 0; hh < 32; hh++) {
        int h = h0 + hh;
        const float4* wr = (const float4*)(Wi_w + (size_t)h * N_INP);
        float acc = __ldg(Wi_b + h) + __ldg(omega + h);
#pragma unroll
        for (int q = 0; q < 7; q++) {
            float4 wv = __ldg(wr + q);
            acc = fmaf(wv.x, xq[q].x, acc);
            acc = fmaf(wv.y, xq[q].y, acc);
            acc = fmaf(wv.z, xq[q].z, acc);
            acc = fmaf(wv.w, xq[q].w, acc);
        }
        g_inp[((size_t)t * N_HID + h) * BATCH + b] = acc;
    }
}

// ---------------- kernel B: persistent scan + fused readout -----------------
// SMEM: [0,128K) wh64[j][16 rows] dup pairs ; [128K,192K) red[2][w][r*16+b] u64
extern __shared__ unsigned char smem_raw[];

__global__ void __launch_bounds__(TPB, 1)
step_kernel(const float* __restrict__ Wh,
            const float* __restrict__ W_out,
            const float* __restrict__ b_out,
            float* __restrict__ out) {
    u64* wh64 = (u64*)smem_raw;                          // [j*16 + r] dup pairs
    u64* redA = (u64*)(smem_raw + 131072);               // step parity 0
    u64* redB = redA + 4096;                             // step parity 1

    int tid  = threadIdx.x;
    int cta  = blockIdx.x;
    int w    = tid >> 5;        // 0..15
    int lane = tid & 31;
    int rg4  = lane >> 3;       // 4 row-groups of 4 rows
    int bp   = lane & 7;        // 8 b-pairs of 2 b
    int rt   = cta >> 1;        // row tile 0..63
    int bt   = cta & 1;         // batch tile 0..1
    int i0   = rt * ROWS_CTA;   // first row
    int b0   = bt * B_CTA;      // first batch

    // Wh rows -> SMEM (transposed, dup-paired): wh64[j*16+r] = dup(Wh[i0+r][j])
    for (int idx = tid; idx < ROWS_CTA * N_HID; idx += TPB) {
        int j = idx & (N_HID - 1);
        int r = idx >> 10;
        unsigned vb = __float_as_uint(Wh[(size_t)(i0 + r) * N_HID + j]);
        wh64[j * 16 + r] = ((u64)vb << 32) | vb;
    }

    // combine thread identity (tid<256): output (row r_, batch bl)
    int r_ = tid >> 4;          // 0..15
    int bl = tid & 15;          // 0..15
    int ig = i0 + (r_ & 15);
    int bg = b0 + bl;
    float st = 0.f, ci = 1.f, si = 0.f;
    if (tid < 256) gX64[0][ig][bg] = pack2(1.f, 0.f);    // cos=1, sin=0
    __syncthreads();
    if (tid == 0) st_rel(&g_pf[(bt * 64 + rt) * 8], 8u); // publish X[0] (counter=8)

    const int j0 = w * 64;
    const ulonglong2* wh_base = (const ulonglong2*)(wh64 + (size_t)j0 * 16 + rg4 * 4);
    unsigned* my_fp = &g_pf[(bt * 64 + rt) * 8];

    for (int t = 0; t < T_STEPS; t++) {
        unsigned need = (unsigned)(8 * (t + 1));
        u64* redbuf = (t & 1) ? redB : redA;

        // inp prefetch (independent of flags)
        float inp_v = 0.f;
        if (tid < 256)
            inp_v = __ldcg(&g_inp[((size_t)t * N_HID + ig) * BATCH + bg]);

        // ---- GEMM: warp w owns j in [64w, 64w+64), gated per 16-j sub-block ----
        u64 acc[8];
#pragma unroll
        for (int k = 0; k < 8; k++) acc[k] = 0ull;

#pragma unroll
        for (int sb = 0; sb < 4; sb++) {
            // RAW: producer tile (4w+sb) published X[t] rows [64w+16sb, +16)
            wait_flag(&g_pf[(bt * 64 + 4 * w + sb) * 8], need);

            const ulonglong2* xp = (const ulonglong2*)&gX64[t][j0 + 16 * sb][b0 + 2 * bp];
            ulonglong2 xq[4];
            xq[0] = __ldcg(xp);
            xq[1] = __ldcg(xp + 16);
            xq[2] = __ldcg(xp + 32);
            xq[3] = __ldcg(xp + 48);
#pragma unroll 8
            for (int ii = 0; ii < 16; ii++) {
                ulonglong2 xc = xq[ii & 3];
                if (ii + 4 < 16) xq[ii & 3] = __ldcg(xp + (ii + 4) * 16);

                int i = 16 * sb + ii;
                ulonglong2 wA = wh_base[i * 8];       // dup rows 4rg4, 4rg4+1
                ulonglong2 wB = wh_base[i * 8 + 1];   // dup rows 4rg4+2, 4rg4+3
                FMA2(acc[0], wA.x, xc.x); FMA2(acc[1], wA.x, xc.y);
                FMA2(acc[2], wA.y, xc.x); FMA2(acc[3], wA.y, xc.y);
                FMA2(acc[4], wB.x, xc.x); FMA2(acc[5], wB.x, xc.y);
                FMA2(acc[6], wB.y, xc.x); FMA2(acc[7], wB.y, xc.y);
            }
        }

        // ---- partials to SMEM: redbuf[w*256 + row*16 + b] ----
        {
            u64* rw = redbuf + (size_t)w * 256 + (rg4 * 4) * 16 + 2 * bp;
#pragma unroll
            for (int rr = 0; rr < 4; rr++) {
                ulonglong2 v;
                v.x = acc[rr * 2];
                v.y = acc[rr * 2 + 1];
                *(ulonglong2*)(rw + rr * 16) = v;
            }
        }
        __syncthreads();   // the ONLY per-step CTA barrier: partials visible

        // ---- combine (warps 0-7): sum 16 K-slices, update state, write X[t+1],
        //      then per-warp release-publish. Warps 8-15 sprint to step t+1. ----
        if (tid < 256) {
            const u64* rp = redbuf + tid;         // r_*16+bl == tid
            u64 s0 = rp[0],        s1 = rp[256],  s2 = rp[512],  s3 = rp[768];
            ADD2(s0, rp[1024]); ADD2(s1, rp[1280]); ADD2(s2, rp[1536]); ADD2(s3, rp[1792]);
            ADD2(s0, rp[2048]); ADD2(s1, rp[2304]); ADD2(s2, rp[2560]); ADD2(s3, rp[2816]);
            ADD2(s0, rp[3072]); ADD2(s1, rp[3328]); ADD2(s2, rp[3584]); ADD2(s3, rp[3840]);
            ADD2(s0, s1); ADD2(s2, s3); ADD2(s0, s2);
            float Cc = lo32(s0), Cs = hi32(s0);
            float coupling = si * Cc - ci * Cs;
            float v = coupling + inp_v + st;
            float r = fmodf(v, TWO_PI_F);
            if (r < 0.f) r += TWO_PI_F;           // == jnp.remainder(v, 2pi)
            st = r;
            float sn, cn;
            sincosf(r, &sn, &cn);
            ci = cn; si = sn;
            gX64[t + 1][ig][bg] = pack2(cn, sn);
            // per-warp publish: all 32 lanes' X stores HB-before the release add
            __syncwarp();
            if (lane == 0) red_add_rel(my_fp, 1u);    // counter -> 8(t+2) when all 8 done
        }
    }

    // ---- fused readout ----
    float* sst = (float*)redA;                    // reuse reduction smem
    __syncthreads();                              // GEMM warps done with redbuf
    if (tid < 256) sst[tid] = st;                 // [r_*16 + bl]
    __syncthreads();
    if (tid < B_CTA * N_OUT) {                    // 160 threads: o = tid/16, b = tid%16
        int o  = tid >> 4;
        int b2 = tid & 15;
        float p = 0.f;
#pragma unroll
        for (int r = 0; r < ROWS_CTA; r++)
            p = fmaf(sst[r * 16 + b2], __ldg(&W_out[(size_t)o * N_HID + i0 + r]), p);
        g_rout[((b0 + b2) * N_OUT + o) * N_RT + rt] = p;
    }
    grid_barrier(tid, cta, 1);
    if (cta == 0 && tid < BATCH * N_OUT) {
        int b2 = tid / N_OUT, o = tid % N_OUT;
        const float4* q = (const float4*)(g_rout + (size_t)(b2 * N_OUT + o) * N_RT);
        float a0 = 0.f, a1 = 0.f, a2 = 0.f, a3 = 0.f;
#pragma unroll
        for (int k = 0; k < 16; k++) {
            float4 v = __ldcg(q + k);
            a0 += v.x; a1 += v.y; a2 += v.z; a3 += v.w;
        }
        out[b2 * N_OUT + o] = ((a0 + a1) + (a2 + a3)) + __ldg(b_out + o);
    }
}

// ---------------- launch ----------------------------------------------------
extern "C" void kernel_launch(void* const* d_in, const int* in_sizes, int n_in,
                              void* d_out, int out_size) {
    const float* x     = (const float*)d_in[0];
    const float* Wi_w  = (const float*)d_in[1];
    const float* Wi_b  = (const float*)d_in[2];
    const float* Wh    = (const float*)d_in[3];
    const float* omega = (const float*)d_in[4];
    const float* W_out = (const float*)d_in[5];
    const float* b_out = (const float*)d_in[6];
    float* out = (float*)d_out;

    const int SMEM_BYTES = 131072 + 65536;   // Wh (128K) + red double buffer (64K)
    cudaFuncSetAttribute(step_kernel,
                         cudaFuncAttributeMaxDynamicSharedMemorySize, SMEM_BYTES);

    prep_kernel<<<dim3(4, T_STEPS), 256>>>(x, Wi_w, Wi_b, omega);
    step_kernel<<<NCTA, TPB, SMEM_BYTES>>>(Wh, W_out, b_out, out);
}

// round 16
// speedup vs baseline: 1.5998x; 1.5998x over previous
#include <cuda_runtime.h>
#include <cstdint>

#define T_STEPS   256
#define BATCH     32
#define N_INP     28
#define N_HID     1024
#define N_OUT     10
#define NCTA      128
#define N_RT      64         // row tiles
#define ROWS_CTA  16         // rows per CTA
#define B_CTA     16         // batches per CTA
#define TPB       512        // 16 warps, warp w owns 64 j
#define TWO_PI_F  6.283185307179586f

typedef unsigned long long u64;

// ---------------- device globals ----------------
__device__ float g_inp[T_STEPS * N_HID * BATCH];            // [t][h][b]
// one X buffer per step: no WAR hazard ever (written once, read once per replay)
__device__ __align__(256) u64 gX64[(T_STEPS + 1)][N_HID][BATCH];  // [t][j][b] = pack(cos,sin)
__device__ unsigned g_flags[NCTA * 8];                      // final-barrier flags
__device__ unsigned g_pf[NCTA * 8];                         // publish flags [bt*64+rt]*8
__device__ float g_rout[BATCH * N_OUT * N_RT];              // readout partials

// packed f32x2 ops
#define FMA2(acc, a, b) \
    asm("fma.rn.f32x2 %0, %1, %2, %0;" : "+l"(acc) : "l"(a), "l"(b))
#define ADD2(acc, b) \
    asm("add.rn.f32x2 %0, %0, %1;" : "+l"(acc) : "l"(b))

__device__ __forceinline__ u64 pack2(float lo, float hi) {
    u64 r;
    asm("mov.b64 %0, {%1, %2};" : "=l"(r) : "f"(lo), "f"(hi));
    return r;
}
__device__ __forceinline__ float lo32(u64 v) { return __uint_as_float((unsigned)v); }
__device__ __forceinline__ float hi32(u64 v) { return __uint_as_float((unsigned)(v >> 32)); }

__device__ __forceinline__ unsigned ld_acq(const unsigned* p) {
    unsigned v;
    asm volatile("ld.global.acquire.gpu.u32 %0, [%1];" : "=r"(v) : "l"(p) : "memory");
    return v;
}
__device__ __forceinline__ void st_rel(unsigned* p, unsigned v) {
    asm volatile("st.global.release.gpu.u32 [%0], %1;" :: "l"(p), "r"(v) : "memory");
}

// single-flag wait, uniform across warp, HW-sleep backoff capped at 128ns
__device__ __forceinline__ void wait_flag(const unsigned* fp, unsigned need) {
    if (ld_acq(fp) >= need) return;            // steady-state fast path
    unsigned ns = 32;
    do {
        __nanosleep(ns);
        if (ns < 128) ns <<= 1;
    } while (ld_acq(fp) < need);
}

// ---------------- final grid barrier (used once, for readout) ---------------
__device__ __forceinline__ void grid_barrier(int tid, int cta, unsigned target) {
    __syncthreads();
    if (tid < 32) {
        if (tid == 0) st_rel(&g_flags[cta * 8], target);
        const unsigned* p0 = &g_flags[(tid +  0) * 8];
        const unsigned* p1 = &g_flags[(tid + 32) * 8];
        const unsigned* p2 = &g_flags[(tid + 64) * 8];
        const unsigned* p3 = &g_flags[(tid + 96) * 8];
        bool pending;
        do {
            pending = (ld_acq(p0) < target) | (ld_acq(p1) < target) |
                      (ld_acq(p2) < target) | (ld_acq(p3) < target);
            if (pending) __nanosleep(64);
        } while (__any_sync(0xFFFFFFFFu, pending));
    }
    __syncthreads();
}

// ---------------- kernel A: input projection + flag reset -------------------
__global__ void __launch_bounds__(256)
prep_kernel(const float* __restrict__ x,
            const float* __restrict__ Wi_w,
            const float* __restrict__ Wi_b,
            const float* __restrict__ omega) {
    int t   = blockIdx.y;
    int hg  = blockIdx.x;
    int tid = threadIdx.x;
    int w   = tid >> 5;
    int b   = tid & 31;

    if (t == 0 && hg == 0 && tid < NCTA) {
        g_flags[tid * 8] = 0;
        g_pf[tid * 8]    = 0;
    }

    float4 xq[7];
    const float4* xrow = (const float4*)(x + (size_t)t * BATCH * N_INP + b * N_INP);
#pragma unroll
    for (int q = 0; q < 7; q++) xq[q] = xrow[q];

    int h0 = hg * 256 + w * 32;
    for (int hh = 0; hh < 32; hh++) {
        int h = h0 + hh;
        const float4* wr = (const float4*)(Wi_w + (size_t)h * N_INP);
        float acc = __ldg(Wi_b + h) + __ldg(omega + h);
#pragma unroll
        for (int q = 0; q < 7; q++) {
            float4 wv = __ldg(wr + q);
            acc = fmaf(wv.x, xq[q].x, acc);
            acc = fmaf(wv.y, xq[q].y, acc);
            acc = fmaf(wv.z, xq[q].z, acc);
            acc = fmaf(wv.w, xq[q].w, acc);
        }
        g_inp[((size_t)t * N_HID + h) * BATCH + b] = acc;
    }
}

// ---------------- kernel B: persistent scan + fused readout -----------------
// SMEM: [0,128K) wh64[j][16 rows] dup pairs ; [128K,192K) red[2][w][r*16+b] u64
extern __shared__ unsigned char smem_raw[];

__global__ void __launch_bounds__(TPB, 1)
step_kernel(const float* __restrict__ Wh,
            const float* __restrict__ W_out,
            const float* __restrict__ b_out,
            float* __restrict__ out) {
    u64* wh64 = (u64*)smem_raw;                          // [j*16 + r] dup pairs
    u64* redA = (u64*)(smem_raw + 131072);               // step parity 0
    u64* redB = redA + 4096;                             // step parity 1

    int tid  = threadIdx.x;
    int cta  = blockIdx.x;
    int w    = tid >> 5;        // 0..15
    int lane = tid & 31;
    int rg4  = lane >> 3;       // 4 row-groups of 4 rows
    int bp   = lane & 7;        // 8 b-pairs of 2 b
    int rt   = cta >> 1;        // row tile 0..63
    int bt   = cta & 1;         // batch tile 0..1
    int i0   = rt * ROWS_CTA;   // first row
    int b0   = bt * B_CTA;      // first batch

    // Wh rows -> SMEM (transposed, dup-paired): wh64[j*16+r] = dup(Wh[i0+r][j])
    for (int idx = tid; idx < ROWS_CTA * N_HID; idx += TPB) {
        int j = idx & (N_HID - 1);
        int r = idx >> 10;
        unsigned vb = __float_as_uint(Wh[(size_t)(i0 + r) * N_HID + j]);
        wh64[j * 16 + r] = ((u64)vb << 32) | vb;
    }

    // combine thread identity (tid<256): output (row r_, batch bl)
    int r_ = tid >> 4;          // 0..15
    int bl = tid & 15;          // 0..15
    int ig = i0 + (r_ & 15);
    int bg = b0 + bl;
    float st = 0.f, ci = 1.f, si = 0.f;
    if (tid < 256) gX64[0][ig][bg] = pack2(1.f, 0.f);    // cos=1, sin=0
    __syncthreads();
    if (tid == 0) st_rel(&g_pf[(bt * 64 + rt) * 8], 1u); // publish X[0]

    const int j0 = w * 64;
    const ulonglong2* wh_base = (const ulonglong2*)(wh64 + (size_t)j0 * 16 + rg4 * 4);
    unsigned* my_fp = &g_pf[(bt * 64 + rt) * 8];

    for (int t = 0; t < T_STEPS; t++) {
        unsigned need = (unsigned)(t + 1);
        u64* redbuf = (t & 1) ? redB : redA;

        // inp prefetch (independent of flags)
        float inp_v = 0.f;
        if (tid < 256)
            inp_v = __ldcg(&g_inp[((size_t)t * N_HID + ig) * BATCH + bg]);

        // ---- GEMM: warp w owns j in [64w, 64w+64), gated per 16-j sub-block ----
        u64 acc[8];
#pragma unroll
        for (int k = 0; k < 8; k++) acc[k] = 0ull;

#pragma unroll
        for (int sb = 0; sb < 4; sb++) {
            // RAW: producer tile (4w+sb) published X[t] rows [64w+16sb, +16)
            wait_flag(&g_pf[(bt * 64 + 4 * w + sb) * 8], need);

            const ulonglong2* xp = (const ulonglong2*)&gX64[t][j0 + 16 * sb][b0 + 2 * bp];
            ulonglong2 xq[4];
            xq[0] = __ldcg(xp);
            xq[1] = __ldcg(xp + 16);
            xq[2] = __ldcg(xp + 32);
            xq[3] = __ldcg(xp + 48);
#pragma unroll 8
            for (int ii = 0; ii < 16; ii++) {
                ulonglong2 xc = xq[ii & 3];
                if (ii + 4 < 16) xq[ii & 3] = __ldcg(xp + (ii + 4) * 16);

                int i = 16 * sb + ii;
                ulonglong2 wA = wh_base[i * 8];       // dup rows 4rg4, 4rg4+1
                ulonglong2 wB = wh_base[i * 8 + 1];   // dup rows 4rg4+2, 4rg4+3
                FMA2(acc[0], wA.x, xc.x); FMA2(acc[1], wA.x, xc.y);
                FMA2(acc[2], wA.y, xc.x); FMA2(acc[3], wA.y, xc.y);
                FMA2(acc[4], wB.x, xc.x); FMA2(acc[5], wB.x, xc.y);
                FMA2(acc[6], wB.y, xc.x); FMA2(acc[7], wB.y, xc.y);
            }
        }

        // ---- partials to SMEM: redbuf[w*256 + row*16 + b] ----
        {
            u64* rw = redbuf + (size_t)w * 256 + (rg4 * 4) * 16 + 2 * bp;
#pragma unroll
            for (int rr = 0; rr < 4; rr++) {
                ulonglong2 v;
                v.x = acc[rr * 2];
                v.y = acc[rr * 2 + 1];
                *(ulonglong2*)(rw + rr * 16) = v;
            }
        }
        __syncthreads();   // the ONLY full-CTA barrier: partials visible

        // ---- combine (warps 0-7) overlapped with warps 8-15's next GEMM ----
        if (tid < 256) {
            const u64* rp = redbuf + tid;         // r_*16+bl == tid
            u64 s0 = rp[0],        s1 = rp[256],  s2 = rp[512],  s3 = rp[768];
            ADD2(s0, rp[1024]); ADD2(s1, rp[1280]); ADD2(s2, rp[1536]); ADD2(s3, rp[1792]);
            ADD2(s0, rp[2048]); ADD2(s1, rp[2304]); ADD2(s2, rp[2560]); ADD2(s3, rp[2816]);
            ADD2(s0, rp[3072]); ADD2(s1, rp[3328]); ADD2(s2, rp[3584]); ADD2(s3, rp[3840]);
            ADD2(s0, s1); ADD2(s2, s3); ADD2(s0, s2);
            float Cc = lo32(s0), Cs = hi32(s0);
            float coupling = si * Cc - ci * Cs;
            float v = coupling + inp_v + st;
            float r = fmodf(v, TWO_PI_F);
            if (r < 0.f) r += TWO_PI_F;           // == jnp.remainder(v, 2pi)
            st = r;
            float sn, cn;
            sincosf(r, &sn, &cn);
            ci = cn; si = sn;
            gX64[t + 1][ig][bg] = pack2(cn, sn);
            // combine-group barrier (id 1, 256 threads) orders all X stores
            asm volatile("bar.sync 1, 256;" ::: "memory");
            if (tid == 0) st_rel(my_fp, (unsigned)(t + 2));   // publish X[t+1]
        }
    }

    // ---- fused readout ----
    float* sst = (float*)redA;                    // reuse reduction smem
    __syncthreads();                              // all warps past the loop
    if (tid < 256) sst[tid] = st;                 // [r_*16 + bl]
    __syncthreads();
    if (tid < B_CTA * N_OUT) {                    // 160 threads: o = tid/16, b = tid%16
        int o  = tid >> 4;
        int b2 = tid & 15;
        float p = 0.f;
#pragma unroll
        for (int r = 0; r < ROWS_CTA; r++)
            p = fmaf(sst[r * 16 + b2], __ldg(&W_out[(size_t)o * N_HID + i0 + r]), p);
        g_rout[((b0 + b2) * N_OUT + o) * N_RT + rt] = p;
    }
    grid_barrier(tid, cta, 1);
    if (cta == 0 && tid < BATCH * N_OUT) {
        int b2 = tid / N_OUT, o = tid % N_OUT;
        const float4* q = (const float4*)(g_rout + (size_t)(b2 * N_OUT + o) * N_RT);
        float a0 = 0.f, a1 = 0.f, a2 = 0.f, a3 = 0.f;
#pragma unroll
        for (int k = 0; k < 16; k++) {
            float4 v = __ldcg(q + k);
            a0 += v.x; a1 += v.y; a2 += v.z; a3 += v.w;
        }
        out[b2 * N_OUT + o] = ((a0 + a1) + (a2 + a3)) + __ldg(b_out + o);
    }
}

// ---------------- launch ----------------------------------------------------
extern "C" void kernel_launch(void* const* d_in, const int* in_sizes, int n_in,
                              void* d_out, int out_size) {
    const float* x     = (const float*)d_in[0];
    const float* Wi_w  = (const float*)d_in[1];
    const float* Wi_b  = (const float*)d_in[2];
    const float* Wh    = (const float*)d_in[3];
    const float* omega = (const float*)d_in[4];
    const float* W_out = (const float*)d_in[5];
    const float* b_out = (const float*)d_in[6];
    float* out = (float*)d_out;

    const int SMEM_BYTES = 131072 + 65536;   // Wh (128K) + red double buffer (64K)
    cudaFuncSetAttribute(step_kernel,
                         cudaFuncAttributeMaxDynamicSharedMemorySize, SMEM_BYTES);

    prep_kernel<<<dim3(4, T_STEPS), 256>>>(x, Wi_w, Wi_b, omega);
    step_kernel<<<NCTA, TPB, SMEM_BYTES>>>(Wh, W_out, b_out, out);
}